// round 3
// baseline (speedup 1.0000x reference)
#include <cuda_runtime.h>

// SmileMoENorm — persistent-strip CTAs, smem-resident affine params.
//
// R1 was co-bound on L1TEX (76%) because every token re-streamed 16 KB of
// gamma/beta through L1. Here each CTA stages the ENTIRE gamma+beta table
// (exactly 64 KB) into shared memory once, then loops over ~295 tokens:
// per token the blended-affine inputs are 4 conflict-free LDS.128 per
// thread. Routing (top-2 of 8 logits) is computed once per token by
// thread 0 and broadcast through smem. Blend/apply uses packed
// fma.rn.f32x2 to halve fma-pipe issue. Single kernel, no scratch.
//
// smem: [0,64K)  SGB: gamma at e*256+h4, beta at 2048+e*256+h4 (float4)
//       [64K, +128) red[2][8] float2 (s,q) warp partials, double buffered
//       [64K+256, +32) info[4] float2 {w0, pairbits}, quad buffered

#define N_TOKENS 131072
#define HIDDEN   1024
#define H4       256
#define EPS      1e-5f
#define GRID     444          // 3 CTAs x 148 SMs
#define NTHREADS 256

#define SMEM_RED_OFF  65536
#define SMEM_INFO_OFF (65536 + 256)
#define SMEM_TOTAL    (65536 + 256 + 64)

typedef unsigned long long ull;

__device__ __forceinline__ ull pack2(float lo, float hi) {
    ull r; asm("mov.b64 %0, {%1, %2};" : "=l"(r) : "f"(lo), "f"(hi)); return r;
}
__device__ __forceinline__ void unpack2(ull v, float& lo, float& hi) {
    asm("mov.b64 {%0, %1}, %2;" : "=f"(lo), "=f"(hi) : "l"(v));
}
__device__ __forceinline__ ull add2(ull a, ull b) {
    ull d; asm("add.rn.f32x2 %0, %1, %2;" : "=l"(d) : "l"(a), "l"(b)); return d;
}
__device__ __forceinline__ ull mul2(ull a, ull b) {
    ull d; asm("mul.rn.f32x2 %0, %1, %2;" : "=l"(d) : "l"(a), "l"(b)); return d;
}
__device__ __forceinline__ ull fma2(ull a, ull b, ull c) {
    ull d; asm("fma.rn.f32x2 %0, %1, %2, %3;" : "=l"(d) : "l"(a), "l"(b), "l"(c)); return d;
}

// top-2 of 8 logits -> {w0, float-bits of e0*8+e1}
__device__ __forceinline__ float2 route(float4 a, float4 b) {
    float l[8] = { a.x, a.y, a.z, a.w, b.x, b.y, b.z, b.w };
    float best = l[0], second = -3.4e38f;
    int e0 = 0, e1 = 1;
    #pragma unroll
    for (int i = 1; i < 8; i++) {
        float v = l[i];
        if (v > best)        { second = best; e1 = e0; best = v; e0 = i; }
        else if (v > second) { second = v; e1 = i; }
    }
    float w0 = 1.0f / (1.0f + __expf(second - best));  // renorm top-2 softmax
    return make_float2(w0, __int_as_float(e0 * 8 + e1));
}

__global__ __launch_bounds__(NTHREADS, 3)
void smile_moe_norm_kernel(const float4* __restrict__ x,
                           const float4* __restrict__ logits4,
                           const float4* __restrict__ gamma,
                           const float4* __restrict__ beta,
                           float4* __restrict__ out) {
    extern __shared__ char smem[];
    float4* SGB  = (float4*)smem;
    float2* red  = (float2*)(smem + SMEM_RED_OFF);
    float2* info = (float2*)(smem + SMEM_INFO_OFF);

    const int tid  = threadIdx.x;
    const int lane = tid & 31;
    const int wid  = tid >> 5;
    const int bid  = blockIdx.x;
    const int ntok = (N_TOKENS - 1 - bid) / GRID + 1;

    // ---- stage gamma/beta (64 KB) into smem, once per CTA -----------------
    #pragma unroll
    for (int e = 0; e < 8; e++) {
        SGB[e * H4 + tid]        = gamma[e * H4 + tid];
        SGB[2048 + e * H4 + tid] = beta [e * H4 + tid];
    }

    const size_t step = (size_t)GRID * H4;      // row stride per iteration

    // ---- x prefetch pipeline, depth 2 -------------------------------------
    const float4* xptr = x + (size_t)bid * H4 + tid;   // row for iter i+2
    float4 xv = xptr[0];
    float4 xp = make_float4(0.f, 0.f, 0.f, 0.f);
    if (ntok > 1) xp = xptr[step];
    xptr += 2 * step;

    // ---- thread-0 routing pipeline, depth 2 --------------------------------
    float4 lA0 = make_float4(0,0,0,0), lA1 = lA0, lB0 = lA0, lB1 = lA0;
    if (tid == 0) {
        float4 a = logits4[(size_t)bid * 2], b = logits4[(size_t)bid * 2 + 1];
        info[0] = route(a, b);                          // token for iter 0
        if (ntok > 1) {
            lA0 = logits4[(size_t)(bid + GRID) * 2];
            lA1 = logits4[(size_t)(bid + GRID) * 2 + 1];
        }
        if (ntok > 2) {
            lB0 = logits4[(size_t)(bid + 2 * GRID) * 2];
            lB1 = logits4[(size_t)(bid + 2 * GRID) * 2 + 1];
        }
    }

    float4* optr = out + (size_t)bid * H4 + tid;

    for (int i = 0; i < ntok; i++) {
        // prefetch x row for iter i+2
        float4 xq = make_float4(0.f, 0.f, 0.f, 0.f);
        if (i + 2 < ntok) xq = xptr[0];
        xptr += step;

        // per-thread partial (s, q), packed; 5 shuffle rounds
        float s = xv.x + xv.y + xv.z + xv.w;
        float q = fmaf(xv.x, xv.x, fmaf(xv.y, xv.y, fmaf(xv.z, xv.z, xv.w * xv.w)));
        ull sq = pack2(s, q);
        #pragma unroll
        for (int o = 16; o; o >>= 1)
            sq = add2(sq, __shfl_xor_sync(0xFFFFFFFFu, sq, o));
        if (lane == 0)
            ((ull*)red)[(i & 1) * 8 + wid] = sq;

        // thread 0: routing info for iter i+1 (quad-buffered), refill pipeline
        if (tid == 0 && i + 1 < ntok) {
            info[(i + 1) & 3] = route(lA0, lA1);
            lA0 = lB0; lA1 = lB1;
            if (i + 3 < ntok) {
                size_t tn = (size_t)(bid) + (size_t)(i + 3) * GRID;
                lB0 = logits4[tn * 2];
                lB1 = logits4[tn * 2 + 1];
            }
        }

        __syncthreads();

        // routing info (broadcast LDS)
        float2 nf = info[i & 3];
        const float w0 = nf.x;
        const int pr = __float_as_int(nf.y);
        const int e0 = pr >> 3, e1 = pr & 7;

        // stage-2 reduce: 4 broadcast LDS.128 + packed add tree
        const ulonglong2* rp = (const ulonglong2*)(red + (i & 1) * 8);
        ulonglong2 r0 = rp[0], r1 = rp[1], r2 = rp[2], r3 = rp[3];
        ull sqt = add2(add2(add2(r0.x, r0.y), add2(r1.x, r1.y)),
                       add2(add2(r2.x, r2.y), add2(r3.x, r3.y)));
        float S, Q; unpack2(sqt, S, Q);
        const float mean = S * (1.0f / HIDDEN);
        const float rstd = rsqrtf(fmaf(-mean, mean, Q * (1.0f / HIDDEN)) + EPS);
        const float mr   = -mean * rstd;

        const ull rstd2 = pack2(rstd, rstd);
        const ull mr2   = pack2(mr, mr);
        const ull w0p   = pack2(w0, w0);
        const ull w1p   = pack2(1.0f - w0, 1.0f - w0);

        // blended affine from smem (conflict-free LDS.128)
        ulonglong2 ge0 = *(const ulonglong2*)(SGB + e0 * H4 + tid);
        ulonglong2 ge1 = *(const ulonglong2*)(SGB + e1 * H4 + tid);
        ulonglong2 be0 = *(const ulonglong2*)(SGB + 2048 + e0 * H4 + tid);
        ulonglong2 be1 = *(const ulonglong2*)(SGB + 2048 + e1 * H4 + tid);

        ull gb0 = fma2(w0p, ge0.x, mul2(w1p, ge1.x));
        ull gb1 = fma2(w0p, ge0.y, mul2(w1p, ge1.y));
        ull bb0 = fma2(w0p, be0.x, mul2(w1p, be1.x));
        ull bb1 = fma2(w0p, be0.y, mul2(w1p, be1.y));

        ull x01 = pack2(xv.x, xv.y), x23 = pack2(xv.z, xv.w);
        ull n0 = fma2(x01, rstd2, mr2);
        ull n1 = fma2(x23, rstd2, mr2);
        ulonglong2 ov;
        ov.x = fma2(n0, gb0, bb0);
        ov.y = fma2(n1, gb1, bb1);
        *(ulonglong2*)optr = ov;
        optr += step;

        xv = xp; xp = xq;
    }
}

extern "C" void kernel_launch(void* const* d_in, const int* in_sizes, int n_in,
                              void* d_out, int out_size) {
    const float4* x       = (const float4*)d_in[0];
    const float4* logits4 = (const float4*)d_in[1];
    const float4* gamma   = (const float4*)d_in[2];
    const float4* beta    = (const float4*)d_in[3];
    float4* out           = (float4*)d_out;

    cudaFuncSetAttribute(smile_moe_norm_kernel,
                         cudaFuncAttributeMaxDynamicSharedMemorySize, SMEM_TOTAL);
    smile_moe_norm_kernel<<<GRID, NTHREADS, SMEM_TOTAL>>>(
        x, logits4, gamma, beta, out);
}

// round 4
// speedup vs baseline: 1.6905x; 1.6905x over previous
#include <cuda_runtime.h>
#include <cuda_fp16.h>

// SmileMoENorm — R1 structure + packed-fp16 gamma/beta table.
//
// R1 was co-bound: L1TEX=76% vs DRAM=74%, with 16 KB/token of blended-affine
// gamma/beta loads making up 2/3 of L1TEX wavefronts. R2 (global sort) and
// R3 (smem staging) both failed because they moved that traffic rather than
// reducing it (LDS shares the L1TEX pipe with LDG). This version SHRINKS it:
// a pre-pass packs (gamma, beta) per element into one half2 table, so the
// epilogue reads 2 fp16 streams (4 KB/token) instead of 4 fp32 streams
// (16 KB/token). Blend in HFMA2, unpack once, finish in f32. Everything
// else is identical to the 176 us R1 kernel.

#define N_TOKENS    131072
#define HIDDEN      1024
#define NUM_EXPERTS 8
#define H4          (HIDDEN / 4)
#define EPS         1e-5f

__device__ __half2 d_pk[NUM_EXPERTS * HIDDEN];   // (gamma, beta) packed per element

// ---- pre-pass: pack gamma/beta into fp16 (runs once per launch, ~2 us) ----
__global__ void k_pack(const float* __restrict__ gamma,
                       const float* __restrict__ beta) {
    const int i = blockIdx.x * blockDim.x + threadIdx.x;   // 0..8191
    d_pk[i] = __floats2half2_rn(gamma[i], beta[i]);
}

// ------------------------------------------------------------- main kernel
__global__ __launch_bounds__(256, 4)
void smile_moe_norm_kernel(const float4* __restrict__ x,
                           const float4* __restrict__ logits4,   // [N,2] float4
                           float4* __restrict__ out) {
    const int warp_in_block = threadIdx.x >> 5;
    const int lane          = threadIdx.x & 31;
    const int token         = blockIdx.x * (blockDim.x >> 5) + warp_in_block;
    if (token >= N_TOKENS) return;

    // ---- router: top-2 of 8 logits, renormalized softmax weights ----------
    const float4 la = logits4[token * 2 + 0];
    const float4 lb = logits4[token * 2 + 1];
    float l[NUM_EXPERTS] = { la.x, la.y, la.z, la.w, lb.x, lb.y, lb.z, lb.w };

    float best = l[0], second = -3.4e38f;
    int   e0 = 0,     e1 = 0;
    #pragma unroll
    for (int i = 1; i < NUM_EXPERTS; i++) {
        float v = l[i];
        if (v > best)        { second = best; e1 = e0; best = v; e0 = i; }
        else if (v > second) { second = v; e1 = i; }
    }
    const float t  = __expf(second - best);     // full-softmax denom cancels
    const float w0 = 1.0f / (1.0f + t);
    const float w1 = 1.0f - w0;
    const __half2 w0h = __float2half2_rn(w0);
    const __half2 w1h = __float2half2_rn(w1);

    // ---- pass over row: registers + warp reduction -------------------------
    const float4* xr = x + (size_t)token * H4;
    float4 v[8];
    float sum = 0.0f, sq = 0.0f;
    #pragma unroll
    for (int k = 0; k < 8; k++) {
        v[k] = xr[lane + 32 * k];
        sum += v[k].x + v[k].y + v[k].z + v[k].w;
        sq  = fmaf(v[k].x, v[k].x, sq);
        sq  = fmaf(v[k].y, v[k].y, sq);
        sq  = fmaf(v[k].z, v[k].z, sq);
        sq  = fmaf(v[k].w, v[k].w, sq);
    }
    #pragma unroll
    for (int off = 16; off > 0; off >>= 1) {
        sum += __shfl_xor_sync(0xFFFFFFFFu, sum, off);
        sq  += __shfl_xor_sync(0xFFFFFFFFu, sq,  off);
    }
    const float mean = sum * (1.0f / HIDDEN);
    const float var  = fmaf(-mean, mean, sq * (1.0f / HIDDEN));
    const float rstd = rsqrtf(var + EPS);
    const float mr   = -mean * rstd;            // normed = x*rstd + mr

    // ---- epilogue: packed-fp16 blended affine + store ----------------------
    const __half2* pk0 = d_pk + e0 * HIDDEN;
    const __half2* pk1 = d_pk + e1 * HIDDEN;
    float4* orow = out + (size_t)token * H4;

    #pragma unroll
    for (int k = 0; k < 8; k++) {
        const int h4 = lane + 32 * k;           // float4 index
        const int h  = 4 * h4;                  // element index
        // 4 (g,b) half2 pairs per expert: one LDG.128 per stream
        const uint4 r0 = *(const uint4*)(pk0 + h);
        const uint4 r1 = *(const uint4*)(pk1 + h);

        __half2 e0w, e1w;
        float2 fb;
        float4 o;
        const float nx = fmaf(v[k].x, rstd, mr);
        const float ny = fmaf(v[k].y, rstd, mr);
        const float nz = fmaf(v[k].z, rstd, mr);
        const float nw = fmaf(v[k].w, rstd, mr);

        e0w = *(const __half2*)&r0.x; e1w = *(const __half2*)&r1.x;
        fb  = __half22float2(__hfma2(e0w, w0h, __hmul2(e1w, w1h)));
        o.x = fmaf(nx, fb.x, fb.y);

        e0w = *(const __half2*)&r0.y; e1w = *(const __half2*)&r1.y;
        fb  = __half22float2(__hfma2(e0w, w0h, __hmul2(e1w, w1h)));
        o.y = fmaf(ny, fb.x, fb.y);

        e0w = *(const __half2*)&r0.z; e1w = *(const __half2*)&r1.z;
        fb  = __half22float2(__hfma2(e0w, w0h, __hmul2(e1w, w1h)));
        o.z = fmaf(nz, fb.x, fb.y);

        e0w = *(const __half2*)&r0.w; e1w = *(const __half2*)&r1.w;
        fb  = __half22float2(__hfma2(e0w, w0h, __hmul2(e1w, w1h)));
        o.w = fmaf(nw, fb.x, fb.y);

        orow[h4] = o;
    }
}

// ------------------------------------------------------------------ launch
extern "C" void kernel_launch(void* const* d_in, const int* in_sizes, int n_in,
                              void* d_out, int out_size) {
    const float4* x       = (const float4*)d_in[0];  // hidden_states [N, H]
    const float4* logits4 = (const float4*)d_in[1];  // router_logits [N, 8]
    const float*  gamma   = (const float*)d_in[2];   // [E, H]
    const float*  beta    = (const float*)d_in[3];   // [E, H]
    float4* out           = (float4*)d_out;

    k_pack<<<(NUM_EXPERTS * HIDDEN) / 256, 256>>>(gamma, beta);

    const int warps_per_block = 8;                   // 256 threads
    const int blocks = N_TOKENS / warps_per_block;   // 16384
    smile_moe_norm_kernel<<<blocks, warps_per_block * 32>>>(x, logits4, out);
}